// round 8
// baseline (speedup 1.0000x reference)
#include <cuda_runtime.h>
#include <cuda_bf16.h>

// Weighted AUC, single fused kernel. R5 structure, but 2x-unrolled mainloop with
// all 6 LDG.128 front-batched (regs allowed up to 42 via launch_bounds(512,3))
// to double per-warp MLP. Labels are exactly 0/1: one smem ATOMS per element
// into [tp NB | fp NB]. area = sum_b fp[b]*(TP_above(b)+0.5*tp[b]);
// auc = area/(TP_tot*FP_tot). Last block per task finalizes and re-zeros
// global state so every graph replay is identical.

#define T_TASKS 16
#define NB 4096                // prediction bins, uniform [0,1)
#define NPT 2097152
#define N4 (NPT / 4)           // 524288 float4 per task
#define CHUNKS 28              // 16*28 = 448 blocks ~= 1 wave at 3 blocks/SM
#define PER_CHUNK 18725        // ceil(N4/28)
#define THREADS 512
#define BINS_PT (NB / THREADS) // 8 bins per thread in finalize

__device__ float        g_hist[T_TASKS * 2 * NB];   // [tp NB][fp NB] per task, zero-init
__device__ unsigned int g_count[T_TASKS];           // zero-init

__global__ void __launch_bounds__(THREADS, 3) auc_kernel(
    const float4* __restrict__ pp, const float4* __restrict__ ll,
    const float4* __restrict__ ww, float* __restrict__ out)
{
    __shared__ __align__(16) float sh[2 * NB];   // 32 KB: [tp NB][fp NB]
    const int task = blockIdx.y;
    const int t    = threadIdx.x;

    for (int i = t; i < 2 * NB; i += THREADS) sh[i] = 0.0f;
    __syncthreads();

    // ---- histogram phase: 2x strided unroll, 6 loads front-batched ----
    {
        const int start = blockIdx.x * PER_CHUNK;
        const int end   = (start + PER_CHUNK < N4) ? start + PER_CHUNK : N4;
        const int base  = task * N4 + start;
        const int cnt   = end - start;

#define DO_COMP(pv, lv, wv, c)                                            \
        {                                                                 \
            int b = (int)(pv.c * (float)NB);                              \
            b = b > NB - 1 ? NB - 1 : b;                                  \
            int off = b + ((lv.c == 0.0f) ? NB : 0);                      \
            atomicAdd(sh + off, wv.c);                                    \
        }

        int i = t;
        for (; i + THREADS < cnt; i += 2 * THREADS) {
            // front-batch all six 128-bit loads
            float4 pa = __ldcs(pp + base + i);
            float4 pb = __ldcs(pp + base + i + THREADS);
            float4 la = __ldcs(ll + base + i);
            float4 lb = __ldcs(ll + base + i + THREADS);
            float4 wa = __ldcs(ww + base + i);
            float4 wb = __ldcs(ww + base + i + THREADS);

            DO_COMP(pa, la, wa, x) DO_COMP(pa, la, wa, y)
            DO_COMP(pa, la, wa, z) DO_COMP(pa, la, wa, w)
            DO_COMP(pb, lb, wb, x) DO_COMP(pb, lb, wb, y)
            DO_COMP(pb, lb, wb, z) DO_COMP(pb, lb, wb, w)
        }
        if (i < cnt) {
            float4 pa = __ldcs(pp + base + i);
            float4 la = __ldcs(ll + base + i);
            float4 wa = __ldcs(ww + base + i);
            DO_COMP(pa, la, wa, x) DO_COMP(pa, la, wa, y)
            DO_COMP(pa, la, wa, z) DO_COMP(pa, la, wa, w)
        }
#undef DO_COMP
    }
    __syncthreads();

    // ---- flush to global ----
    float* gh = g_hist + task * 2 * NB;
    for (int i = t; i < 2 * NB; i += THREADS) {
        float v = sh[i];
        if (v != 0.0f) atomicAdd(gh + i, v);
    }
    __threadfence();
    __syncthreads();

    // ---- elect last block per task ----
    __shared__ unsigned s_last;
    if (t == 0) s_last = atomicAdd(&g_count[task], 1u);
    __syncthreads();
    if (s_last != CHUNKS - 1) return;
    __threadfence();   // acquire: see all other blocks' hist atomics

    // ---- finalize (this block only): suffix scan + area + auc ----
    float* fsum = sh;                 // reuse smem (512 floats)
    float  th[BINS_PT], loc[BINS_PT];
    float  s = 0.0f;
#pragma unroll
    for (int j = BINS_PT - 1; j >= 0; --j) {
        th[j] = gh[t * BINS_PT + j];
        s += th[j];
        loc[j] = s;                   // inclusive suffix within thread's bins
    }
    __syncthreads();
    fsum[t] = s;
    __syncthreads();

    // Hillis-Steele inclusive suffix scan over 512 thread totals
    for (int off = 1; off < THREADS; off <<= 1) {
        float v = (t + off < THREADS) ? fsum[t + off] : 0.0f;
        __syncthreads();
        fsum[t] += v;
        __syncthreads();
    }
    const float above    = (t + 1 < THREADS) ? fsum[t + 1] : 0.0f;
    const float tp_total = fsum[0];
    __syncthreads();

    double a = 0.0, f = 0.0;
#pragma unroll
    for (int j = 0; j < BINS_PT; ++j) {
        float fv  = gh[NB + t * BINS_PT + j];
        float lut = above + loc[j] - 0.5f * th[j];
        a += (double)fv * (double)lut;
        f += (double)fv;
    }

#pragma unroll
    for (int off = 16; off; off >>= 1) {
        a += __shfl_down_sync(0xffffffffu, a, off);
        f += __shfl_down_sync(0xffffffffu, f, off);
    }
    double* sred = (double*)sh;       // reuse smem (32 doubles)
    const int warp = t >> 5, lane = t & 31;
    __syncthreads();
    if (lane == 0) { sred[warp] = a; sred[16 + warp] = f; }
    __syncthreads();

    if (t == 0) {
        double ta = 0.0, tf = 0.0;
#pragma unroll
        for (int k = 0; k < THREADS / 32; ++k) { ta += sred[k]; tf += sred[16 + k]; }
        double denom = tf * (double)tp_total;
        out[task] = (denom == 0.0) ? 0.5f : (float)(ta / denom);
        g_count[task] = 0u;           // restore invariant
    }

    // restore g_hist zeros for next call / replay
    for (int i = t; i < 2 * NB; i += THREADS) gh[i] = 0.0f;
}

extern "C" void kernel_launch(void* const* d_in, const int* in_sizes, int n_in,
                              void* d_out, int out_size) {
    int off = (n_in >= 4 && in_sizes[0] == 1) ? 1 : 0;
    const float4* p = (const float4*)d_in[off + 0];
    const float4* l = (const float4*)d_in[off + 1];
    const float4* w = (const float4*)d_in[off + 2];

    dim3 g(CHUNKS, T_TASKS);
    auc_kernel<<<g, THREADS>>>(p, l, w, (float*)d_out);
}

// round 9
// speedup vs baseline: 1.5109x; 1.5109x over previous
#include <cuda_runtime.h>
#include <cuda_bf16.h>

// Weighted AUC, single fused kernel (R5 skeleton + instruction-diet mainloop).
// Labels are exactly 0/1: each element does ONE smem ATOMS into [tp NB | fp NB],
// with the bin+half select folded into two FMAs + F2I:
//   off = (int)fma(l, -NB, fma(p, NB, NB))   (exact: values < 2^13, lsb 2^-11)
// area = sum_b fp[b]*(TP_above(b)+0.5*tp[b]); auc = area/(TP_tot*FP_tot).
// Last block per task finalizes in-kernel and restores zeroed global state so
// every graph replay is identical.

#define T_TASKS 16
#define NB 4096                // prediction bins, uniform [0,1)
#define NPT 2097152
#define N4 (NPT / 4)           // 524288 float4 per task
#define CHUNKS 37              // 16*37 = 592 blocks = 4 per SM on 148 SMs
#define PER_CHUNK 14171        // ceil(N4/37)
#define THREADS 512
#define BINS_PT (NB / THREADS) // 8 bins per thread in finalize

__device__ float        g_hist[T_TASKS * 2 * NB];   // [tp NB][fp NB] per task, zero-init
__device__ unsigned int g_count[T_TASKS];           // zero-init

__global__ void __launch_bounds__(THREADS, 4) auc_kernel(
    const float4* __restrict__ pp, const float4* __restrict__ ll,
    const float4* __restrict__ ww, float* __restrict__ out)
{
    __shared__ __align__(16) float sh[2 * NB];   // 32 KB: [tp NB][fp NB]
    const int task = blockIdx.y;
    const int t    = threadIdx.x;

    for (int i = t; i < 2 * NB; i += THREADS) sh[i] = 0.0f;
    __syncthreads();

    // ---- histogram phase ----
    {
        const int start = blockIdx.x * PER_CHUNK;
        const int end   = (start + PER_CHUNK < N4) ? start + PER_CHUNK : N4;
        const int base  = task * N4 + start;
        const int cnt   = end - start;

#pragma unroll 2
        for (int i = t; i < cnt; i += THREADS) {
            float4 pv = __ldcs(pp + base + i);
            float4 lv = __ldcs(ll + base + i);
            float4 wv = __ldcs(ww + base + i);
            // off = bin(p) + (label ? 0 : NB), via 2 FMA + 1 F2I (no clamps:
            // p in [0,1) so p*NB in [0,NB); label is exactly 0.0 or 1.0)
#define DO_COMP(c)                                                        \
            {                                                             \
                float offf = fmaf(lv.c, -(float)NB,                       \
                                  fmaf(pv.c, (float)NB, (float)NB));      \
                atomicAdd(sh + (int)offf, wv.c);                          \
            }
            DO_COMP(x) DO_COMP(y) DO_COMP(z) DO_COMP(w)
#undef DO_COMP
        }
    }
    __syncthreads();

    // ---- flush to global ----
    float* gh = g_hist + task * 2 * NB;
    for (int i = t; i < 2 * NB; i += THREADS)
        atomicAdd(gh + i, sh[i]);
    __threadfence();
    __syncthreads();

    // ---- elect last block per task ----
    __shared__ unsigned s_last;
    if (t == 0) s_last = atomicAdd(&g_count[task], 1u);
    __syncthreads();
    if (s_last != CHUNKS - 1) return;
    __threadfence();   // acquire: see all other blocks' hist atomics

    // ---- finalize (this block only): suffix scan + area + auc ----
    float* fsum = sh;                 // reuse smem (512 floats)
    float  th[BINS_PT], loc[BINS_PT];
    float  s = 0.0f;
#pragma unroll
    for (int j = BINS_PT - 1; j >= 0; --j) {
        th[j] = gh[t * BINS_PT + j];
        s += th[j];
        loc[j] = s;                   // inclusive suffix within thread's bins
    }
    __syncthreads();
    fsum[t] = s;
    __syncthreads();

    // Hillis-Steele inclusive suffix scan over 512 thread totals
    for (int off = 1; off < THREADS; off <<= 1) {
        float v = (t + off < THREADS) ? fsum[t + off] : 0.0f;
        __syncthreads();
        fsum[t] += v;
        __syncthreads();
    }
    const float above    = (t + 1 < THREADS) ? fsum[t + 1] : 0.0f;
    const float tp_total = fsum[0];
    __syncthreads();

    double a = 0.0, f = 0.0;
#pragma unroll
    for (int j = 0; j < BINS_PT; ++j) {
        float fv  = gh[NB + t * BINS_PT + j];
        float lut = above + loc[j] - 0.5f * th[j];
        a += (double)fv * (double)lut;
        f += (double)fv;
    }

#pragma unroll
    for (int off = 16; off; off >>= 1) {
        a += __shfl_down_sync(0xffffffffu, a, off);
        f += __shfl_down_sync(0xffffffffu, f, off);
    }
    double* sred = (double*)sh;       // reuse smem (32 doubles)
    const int warp = t >> 5, lane = t & 31;
    __syncthreads();
    if (lane == 0) { sred[warp] = a; sred[16 + warp] = f; }
    __syncthreads();

    if (t == 0) {
        double ta = 0.0, tf = 0.0;
#pragma unroll
        for (int k = 0; k < THREADS / 32; ++k) { ta += sred[k]; tf += sred[16 + k]; }
        double denom = tf * (double)tp_total;
        out[task] = (denom == 0.0) ? 0.5f : (float)(ta / denom);
        g_count[task] = 0u;           // restore invariant
    }

    // restore g_hist zeros for next call / replay
    for (int i = t; i < 2 * NB; i += THREADS) gh[i] = 0.0f;
}

extern "C" void kernel_launch(void* const* d_in, const int* in_sizes, int n_in,
                              void* d_out, int out_size) {
    int off = (n_in >= 4 && in_sizes[0] == 1) ? 1 : 0;
    const float4* p = (const float4*)d_in[off + 0];
    const float4* l = (const float4*)d_in[off + 1];
    const float4* w = (const float4*)d_in[off + 2];

    dim3 g(CHUNKS, T_TASKS);
    auc_kernel<<<g, THREADS>>>(p, l, w, (float*)d_out);
}